// round 12
// baseline (speedup 1.0000x reference)
#include <cuda_runtime.h>
#include <cuda_fp16.h>
#include <math.h>

#define NN 100000
#define EE 1600000
#define ENE (EE + NN)
#define NAUG 136          // 128 H cols + 4 als + 4 ald
#define BSTRIDE 136       // smem row stride (halfs): 272B, conflict-free
#define SMEM_MMA (2 * 128 * 136 * 2)   // A + B tiles in halfs -> bytes

// ---------------- scratch (device globals; no allocation allowed) ----------
__device__ __half g_hh[NN * 128];   // projected features (fp16)
__device__ __half g_xh[NN * 128];   // activations (fp16)
__device__ float  g_h2[NN * 2];     // layer-2 projected features
__device__ float  g_als[NN * 4];    // per-node src attention logits
__device__ float  g_ald[NN * 4];    // per-node dst attention logits
__device__ float  g_als2[NN];       // layer-2 src logits
__device__ float  g_ald2[NN];       // layer-2 dst logits
__device__ int    g_src[ENE];       // decoded src indices (+self loops)
__device__ int    g_dst[ENE];       // decoded dst indices (+self loops)
__device__ int    g_csr[ENE];       // src indices sorted by dst
__device__ int    g_off[NN + 1];    // CSR row offsets (by dst)
__device__ int    g_deg[NN];        // degree count (zero-initialized at load; re-zeroed each call)
__device__ int    g_incl[NN];       // block-inclusive scan scratch
__device__ int    g_woff[NN];       // scatter write cursors
__device__ int    g_bsum[512];      // block sums
__device__ __half g_waug0[128 * NAUG]; // augmented fp16 weights layer 0
__device__ __half g_waug1[128 * NAUG]; // augmented fp16 weights layer 1

// ---------------- helpers ---------------------------------------------------
__device__ __forceinline__ float lrelu(float v) { return v > 0.0f ? v : 0.2f * v; }

__device__ __forceinline__ void ldsm_x4(unsigned* r, unsigned addr) {
    asm volatile("ldmatrix.sync.aligned.m8n8.x4.shared.b16 {%0,%1,%2,%3}, [%4];"
        : "=r"(r[0]), "=r"(r[1]), "=r"(r[2]), "=r"(r[3]) : "r"(addr));
}
__device__ __forceinline__ void ldsm_x4_trans(unsigned* r, unsigned addr) {
    asm volatile("ldmatrix.sync.aligned.m8n8.x4.trans.shared.b16 {%0,%1,%2,%3}, [%4];"
        : "=r"(r[0]), "=r"(r[1]), "=r"(r[2]), "=r"(r[3]) : "r"(addr));
}
__device__ __forceinline__ void ldsm_x2_trans(unsigned* r, unsigned addr) {
    asm volatile("ldmatrix.sync.aligned.m8n8.x2.trans.shared.b16 {%0,%1}, [%2];"
        : "=r"(r[0]), "=r"(r[1]) : "r"(addr));
}
__device__ __forceinline__ void mma16816(float* d, const unsigned* a, const unsigned* b) {
    asm volatile("mma.sync.aligned.m16n8k16.row.col.f32.f16.f16.f32 "
        "{%0,%1,%2,%3}, {%4,%5,%6,%7}, {%8,%9}, {%0,%1,%2,%3};"
        : "+f"(d[0]), "+f"(d[1]), "+f"(d[2]), "+f"(d[3])
        : "r"(a[0]), "r"(a[1]), "r"(a[2]), "r"(a[3]), "r"(b[0]), "r"(b[1]));
}
__device__ __forceinline__ float4 h4f(uint2 u) {
    __half2 p0 = *(__half2*)&u.x, p1 = *(__half2*)&u.y;
    float2 f0 = __half22float2(p0), f1 = __half22float2(p1);
    return make_float4(f0.x, f0.y, f1.x, f1.y);
}
__device__ __forceinline__ void cpasync16(unsigned daddr, const void* g, unsigned srcsz) {
    asm volatile("cp.async.ca.shared.global [%0], [%1], 16, %2;"
                 :: "r"(daddr), "l"(g), "r"(srcsz));
}
__device__ __forceinline__ void cpasync16cg(unsigned daddr, const void* g) {
    asm volatile("cp.async.cg.shared.global [%0], [%1], 16;"
                 :: "r"(daddr), "l"(g));
}

// ---------------- augmented weights (both layers) + deg zero -----------------
__global__ void build_waug2(const float* __restrict__ W0, const float* __restrict__ as0,
                            const float* __restrict__ ad0, const float* __restrict__ W1,
                            const float* __restrict__ as1, const float* __restrict__ ad1,
                            __half* __restrict__ wg0, __half* __restrict__ wg1,
                            int* deg, int n) {
    int b = blockIdx.x, t = threadIdx.x;
    if (b < 130) {
        const float* W  = (b < 65) ? W0 : W1;
        const float* as = (b < 65) ? as0 : as1;
        const float* ad = (b < 65) ? ad0 : ad1;
        __half* wg = (b < 65) ? wg0 : wg1;
        int bb = (b < 65) ? b : b - 65;
        if (bb < 64) {
            int i = bb * 256 + t;
            wg[(i >> 7) * NAUG + (i & 127)] = __float2half(W[i]);
        } else {
#pragma unroll
            for (int j = 0; j < 4; j++) {
                int idx = j * 256 + t;
                int k = idx >> 3, hcol = idx & 7;
                int h = hcol & 3;
                const float* av = (hcol < 4) ? as : ad;
                float sum = 0.f;
#pragma unroll
                for (int cc = 0; cc < 32; cc++)
                    sum += W[k * 128 + h * 32 + cc] * av[h * 32 + cc];
                wg[k * NAUG + 128 + ((hcol < 4) ? 0 : 4) + h] = __float2half(sum);
            }
        }
    } else {
        int i = (b - 130) * 256 + t;
        if (i < n) deg[i] = 0;
    }
}

// ---------------- decode + inline dtype detection + degree count -------------
__device__ __forceinline__ int detect_is64(const unsigned* w, int e) {
    int allz = 1;
#pragma unroll
    for (int k = 0; k < 8; k++) {
        long long idx = 2LL * (((long long)k * e) / 8) + 1;
        allz &= (w[idx] == 0u) ? 1 : 0;
    }
    return allz;
}

__global__ void decode_edges(const void* __restrict__ ei, int* __restrict__ src,
                             int* __restrict__ dst, int* deg, int e, int n) {
    int i = blockIdx.x * blockDim.x + threadIdx.x;
    if (i >= e + n) return;
    int s, d;
    if (i < e) {
        if (detect_is64((const unsigned*)ei, e)) {
            const long long* p = (const long long*)ei;
            s = (int)p[i]; d = (int)p[e + i];
        } else {
            const int* p = (const int*)ei;
            s = p[i]; d = p[e + i];
        }
    } else {
        s = d = i - e;
    }
    src[i] = s;
    dst[i] = d;
    atomicAdd(&deg[d], 1);
}

__global__ void scan1(const int* __restrict__ deg, int* __restrict__ incl,
                      int* __restrict__ bsum, int n) {
    __shared__ int sm[256];
    int i = blockIdx.x * 256 + threadIdx.x;
    int v = (i < n) ? deg[i] : 0;
    sm[threadIdx.x] = v;
    __syncthreads();
#pragma unroll
    for (int o = 1; o < 256; o <<= 1) {
        int t = (threadIdx.x >= o) ? sm[threadIdx.x - o] : 0;
        __syncthreads();
        sm[threadIdx.x] += t;
        __syncthreads();
    }
    if (i < n) incl[i] = sm[threadIdx.x];
    if (threadIdx.x == 255) bsum[blockIdx.x] = sm[255];
}

__global__ void scan2(int* bsum, int nb) {
    __shared__ int sm[512];
    int t = threadIdx.x;
    sm[t] = (t < nb) ? bsum[t] : 0;
    __syncthreads();
#pragma unroll
    for (int o = 1; o < 512; o <<= 1) {
        int v = (t >= o) ? sm[t - o] : 0;
        __syncthreads();
        sm[t] += v;
        __syncthreads();
    }
    if (t < nb) bsum[t] = sm[t];
}

__global__ void scan3(const int* __restrict__ incl, const int* __restrict__ deg,
                      const int* __restrict__ bsum, int* __restrict__ off,
                      int* __restrict__ woff, int n, int tot) {
    int i = blockIdx.x * blockDim.x + threadIdx.x;
    if (i >= n) return;
    int b = i >> 8;
    int o = incl[i] - deg[i] + (b > 0 ? bsum[b - 1] : 0);
    off[i] = o;
    woff[i] = o;
    if (i == 0) off[n] = tot;
}

__global__ void scatter_csr(const int* __restrict__ src, const int* __restrict__ dst,
                            int* woff, int* __restrict__ csr, int tot) {
    int i = blockIdx.x * blockDim.x + threadIdx.x;
    if (i >= tot) return;
    int pos = atomicAdd(&woff[dst[i]], 1);
    csr[pos] = src[i];
}

// ---------------- tensor-core GEMM: [H | als | ald] = X @ W' -----------------
template <bool FP32IN>
__global__ void __launch_bounds__(256, 2) gemm_mma(const void* __restrict__ Xv,
                                                   const __half* __restrict__ waug,
                                                   __half* __restrict__ Hout,
                                                   float* __restrict__ als,
                                                   float* __restrict__ ald, int n) {
    extern __shared__ __half smh[];
    __half* As = smh;
    __half* Bs = smh + 128 * BSTRIDE;
    const int t = threadIdx.x;
    const int w = t >> 5, lane = t & 31;
    const int row0 = blockIdx.x * 128;

    const unsigned As_base = (unsigned)__cvta_generic_to_shared(As);
    const unsigned Bs_base = (unsigned)__cvta_generic_to_shared(Bs);

    for (int i = t; i < 2176; i += 256)
        cpasync16(Bs_base + i * 16, (const uint4*)waug + i, 16u);

    if (FP32IN) {
        const float* X = (const float*)Xv;
        for (int i = t; i < 128 * 16; i += 256) {
            int r = i >> 4, q = i & 15;
            float4 v0 = make_float4(0.f, 0.f, 0.f, 0.f), v1 = v0;
            if (row0 + r < n) {
                v0 = ((const float4*)X)[(size_t)(row0 + r) * 32 + q * 2];
                v1 = ((const float4*)X)[(size_t)(row0 + r) * 32 + q * 2 + 1];
            }
            __half2 h0 = __floats2half2_rn(v0.x, v0.y), h1 = __floats2half2_rn(v0.z, v0.w);
            __half2 h2 = __floats2half2_rn(v1.x, v1.y), h3 = __floats2half2_rn(v1.z, v1.w);
            uint4 pk = make_uint4(*(unsigned*)&h0, *(unsigned*)&h1,
                                  *(unsigned*)&h2, *(unsigned*)&h3);
            *(uint4*)(As + r * BSTRIDE + q * 8) = pk;
        }
    } else {
        const __half* Xh = (const __half*)Xv;
        for (int i = t; i < 128 * 16; i += 256) {
            int r = i >> 4, q = i & 15;
            unsigned sz = (row0 + r < n) ? 16u : 0u;
            cpasync16(As_base + (r * BSTRIDE + q * 8) * 2,
                      (const uint4*)Xh + (size_t)(row0 + r) * 16 + q, sz);
        }
    }
    asm volatile("cp.async.commit_group;");
    asm volatile("cp.async.wait_group 0;" ::: "memory");
    __syncthreads();

    float d[17][4] = {};
#pragma unroll
    for (int kt = 0; kt < 8; kt++) {
        unsigned a[4];
        ldsm_x4(a, As_base +
            (unsigned)(((w * 16 + (lane & 15)) * BSTRIDE + kt * 16 + (lane >> 4) * 8) * 2));
        unsigned b[17][2];
#pragma unroll
        for (int np = 0; np < 8; np++) {
            unsigned r[4];
            ldsm_x4_trans(r, Bs_base +
                (unsigned)(((kt * 16 + (lane & 15)) * BSTRIDE + np * 16 + (lane >> 4) * 8) * 2));
            b[2 * np][0] = r[0]; b[2 * np][1] = r[1];
            b[2 * np + 1][0] = r[2]; b[2 * np + 1][1] = r[3];
        }
        ldsm_x2_trans(b[16], Bs_base +
            (unsigned)(((kt * 16 + (lane & 15)) * BSTRIDE + 128) * 2));
#pragma unroll
        for (int nt = 0; nt < 17; nt++) mma16816(d[nt], a, b[nt]);
    }

    const int g = lane >> 2, i2 = lane & 3;
    const int r0 = row0 + w * 16 + g, r1 = r0 + 8;
#pragma unroll
    for (int nt = 0; nt < 16; nt++) {
        int c = nt * 8 + 2 * i2;
        if (r0 < n) *(__half2*)&Hout[(size_t)r0 * 128 + c] = __floats2half2_rn(d[nt][0], d[nt][1]);
        if (r1 < n) *(__half2*)&Hout[(size_t)r1 * 128 + c] = __floats2half2_rn(d[nt][2], d[nt][3]);
    }
    {
        int j = 2 * i2;
        float* pp = (j < 4) ? als : ald;
        int jj = j & 3;
        if (r0 < n) { pp[r0 * 4 + jj] = d[16][0]; pp[r0 * 4 + jj + 1] = d[16][1]; }
        if (r1 < n) { pp[r1 * 4 + jj] = d[16][2]; pp[r1 * 4 + jj + 1] = d[16][3]; }
    }
}

// ---------------- CSR aggregation, cp.async double-buffered gather -----------
// warp per dst node; 8 edges per stage; two stages in flight.
__global__ void __launch_bounds__(256) csr_layer(
        const int* __restrict__ off, const int* __restrict__ csr,
        const float* __restrict__ als, const float* __restrict__ ald,
        const __half* __restrict__ Hm,
        const float* __restrict__ b, const float* __restrict__ gm,
        const float* __restrict__ be, const float* __restrict__ mu,
        const float* __restrict__ var,
        __half* __restrict__ xo,
        const float* __restrict__ W2, const float* __restrict__ as2,
        const float* __restrict__ ad2, float* __restrict__ h2,
        float* __restrict__ als2, float* __restrict__ ald2, int n) {
    __shared__ __align__(16) __half hbuf[8][2][8][128];  // 32 KB
    __shared__ __align__(16) float  abuf[8][2][8][4];    // 2 KB
    const int d = (blockIdx.x * blockDim.x + threadIdx.x) >> 5;
    const int w = threadIdx.x >> 5;
    const int lane = threadIdx.x & 31;
    if (d >= n) return;
    const int head = lane >> 3;
    const int beg = off[d], end = off[d + 1];
    const float aldv = ald[d * 4 + head];
    const int nst = (end - beg + 7) >> 3;

    const unsigned hb0 = (unsigned)__cvta_generic_to_shared(&hbuf[w][0][0][0]);
    const unsigned ab0 = (unsigned)__cvta_generic_to_shared(&abuf[w][0][0][0]);

    // issue one stage of cp.asyncs (8 edges) into buffer bf
    auto issue = [&](int base, int bf) {
        int idx = 0;
        if (lane < 8) {
            int jj = base + lane;
            if (jj < end) idx = csr[jj];
        }
        unsigned hdst = hb0 + (unsigned)(bf * 8 * 256) + (lane & 15) * 16;
#pragma unroll
        for (int k = 0; k < 4; k++) {
            int eI = 2 * k + (lane >> 4);
            int s = __shfl_sync(0xffffffffu, idx, eI);
            cpasync16cg(hdst + (unsigned)(eI * 256),
                        Hm + (size_t)s * 128 + (lane & 15) * 8);
        }
        if (lane < 8)
            cpasync16cg(ab0 + (unsigned)(bf * 8 * 16 + lane * 16),
                        als + (size_t)idx * 4);
        asm volatile("cp.async.commit_group;");
    };

    float4 a = make_float4(0.f, 0.f, 0.f, 0.f);
    float den = 0.f;

    int base = beg;
    issue(base, 0);
    for (int st = 0; st < nst; st++) {
        int bf = st & 1;
        if (st + 1 < nst) {
            issue(base + 8, bf ^ 1);
            asm volatile("cp.async.wait_group 1;" ::: "memory");
        } else {
            asm volatile("cp.async.wait_group 0;" ::: "memory");
        }
        __syncwarp();
        int cnt = min(8, end - base);
        for (int e2 = 0; e2 < cnt; e2++) {
            float lv = abuf[w][bf][e2][head];
            float ee = __expf(lrelu(lv + aldv));
            uint2 u = *(uint2*)&hbuf[w][bf][e2][lane * 4];
            float4 hv = h4f(u);
            a.x += hv.x * ee;
            a.y += hv.y * ee;
            a.z += hv.z * ee;
            a.w += hv.w * ee;
            den += ee;
        }
        __syncwarp();
        base += 8;
    }

    float inv = 1.0f / (den + 1e-16f);
    float4 b4  = ((const float4*)b)[lane];
    float4 gm4 = ((const float4*)gm)[lane];
    float4 be4 = ((const float4*)be)[lane];
    float4 mu4 = ((const float4*)mu)[lane];
    float4 v4  = ((const float4*)var)[lane];
    float4 o;
    float t;
    t = a.x * inv + b4.x; t = (t - mu4.x) * rsqrtf(v4.x + 1e-5f) * gm4.x + be4.x; o.x = t > 0.f ? t : expm1f(t);
    t = a.y * inv + b4.y; t = (t - mu4.y) * rsqrtf(v4.y + 1e-5f) * gm4.y + be4.y; o.y = t > 0.f ? t : expm1f(t);
    t = a.z * inv + b4.z; t = (t - mu4.z) * rsqrtf(v4.z + 1e-5f) * gm4.z + be4.z; o.z = t > 0.f ? t : expm1f(t);
    t = a.w * inv + b4.w; t = (t - mu4.w) * rsqrtf(v4.w + 1e-5f) * gm4.w + be4.w; o.w = t > 0.f ? t : expm1f(t);
    __half2 p0 = __floats2half2_rn(o.x, o.y), p1 = __floats2half2_rn(o.z, o.w);
    ((uint2*)xo)[(size_t)d * 32 + lane] = make_uint2(*(unsigned*)&p0, *(unsigned*)&p1);

    if (W2) {  // fused layer-2 projection
        float4 w0 = ((const float4*)W2)[lane * 2];
        float4 w1 = ((const float4*)W2)[lane * 2 + 1];
        float c0 = o.x * w0.x + o.y * w0.z + o.z * w1.x + o.w * w1.z;
        float c1 = o.x * w0.y + o.y * w0.w + o.z * w1.y + o.w * w1.w;
#pragma unroll
        for (int oo = 16; oo > 0; oo >>= 1) {
            c0 += __shfl_down_sync(0xffffffffu, c0, oo);
            c1 += __shfl_down_sync(0xffffffffu, c1, oo);
        }
        if (lane == 0) {
            h2[d * 2]     = c0;
            h2[d * 2 + 1] = c1;
            als2[d] = c0 * as2[0] + c1 * as2[1];
            ald2[d] = c0 * ad2[0] + c1 * ad2[1];
        }
    }
}

// ---------------- CSR output aggregation (warp per dst, lanes over edges) ----
__global__ void csr_out(const int* __restrict__ off, const int* __restrict__ csr,
                        const float* __restrict__ als, const float* __restrict__ ald,
                        const float* __restrict__ h2, const float* __restrict__ b2,
                        float* __restrict__ out, int n) {
    int d = (blockIdx.x * blockDim.x + threadIdx.x) >> 5;
    int lane = threadIdx.x & 31;
    if (d >= n) return;
    const int beg = off[d], end = off[d + 1];
    const float aldv = ald[d];
    float a0 = 0.f, a1 = 0.f, den = 0.f;
    for (int j = beg + lane; j < end; j += 32) {
        int s = csr[j];
        float ee = __expf(lrelu(als[s] + aldv));
        float2 hv = ((const float2*)h2)[s];
        a0 += hv.x * ee;
        a1 += hv.y * ee;
        den += ee;
    }
#pragma unroll
    for (int o = 16; o > 0; o >>= 1) {
        a0  += __shfl_down_sync(0xffffffffu, a0, o);
        a1  += __shfl_down_sync(0xffffffffu, a1, o);
        den += __shfl_down_sync(0xffffffffu, den, o);
    }
    if (lane == 0) {
        float inv = 1.0f / (den + 1e-16f);
        out[d * 2]     = a0 * inv + b2[0];
        out[d * 2 + 1] = a1 * inv + b2[1];
    }
}

// ---------------- host ------------------------------------------------------
extern "C" void kernel_launch(void* const* d_in, const int* in_sizes, int n_in,
                              void* d_out, int out_size) {
    const float* x  = (const float*)d_in[0];
    const void*  ei = d_in[1];
    const float *W0 = (const float*)d_in[2],  *as0 = (const float*)d_in[3],
                *ad0 = (const float*)d_in[4], *b0 = (const float*)d_in[5],
                *gg0 = (const float*)d_in[6], *be0 = (const float*)d_in[7],
                *m0 = (const float*)d_in[8],  *v0 = (const float*)d_in[9];
    const float *W1 = (const float*)d_in[10], *as1 = (const float*)d_in[11],
                *ad1 = (const float*)d_in[12],*b1 = (const float*)d_in[13],
                *gg1 = (const float*)d_in[14],*be1 = (const float*)d_in[15],
                *m1 = (const float*)d_in[16], *v1 = (const float*)d_in[17];
    const float *W2 = (const float*)d_in[18], *as2 = (const float*)d_in[19],
                *ad2 = (const float*)d_in[20],*b2 = (const float*)d_in[21];
    float* out = (float*)d_out;

    const int n = in_sizes[0] / 128;
    const int e = in_sizes[1] / 2;
    const int tot = e + n;

    void* p;
    cudaGetSymbolAddress(&p, g_hh);    __half* hhB   = (__half*)p;
    cudaGetSymbolAddress(&p, g_xh);    __half* xhB   = (__half*)p;
    cudaGetSymbolAddress(&p, g_h2);    float*  h2B   = (float*)p;
    cudaGetSymbolAddress(&p, g_als);   float*  alsB  = (float*)p;
    cudaGetSymbolAddress(&p, g_ald);   float*  aldB  = (float*)p;
    cudaGetSymbolAddress(&p, g_als2);  float*  als2B = (float*)p;
    cudaGetSymbolAddress(&p, g_ald2);  float*  ald2B = (float*)p;
    cudaGetSymbolAddress(&p, g_src);   int*    srcB  = (int*)p;
    cudaGetSymbolAddress(&p, g_dst);   int*    dstB  = (int*)p;
    cudaGetSymbolAddress(&p, g_csr);   int*    csrB  = (int*)p;
    cudaGetSymbolAddress(&p, g_off);   int*    offB  = (int*)p;
    cudaGetSymbolAddress(&p, g_deg);   int*    degB  = (int*)p;
    cudaGetSymbolAddress(&p, g_incl);  int*    inclB = (int*)p;
    cudaGetSymbolAddress(&p, g_woff);  int*    woffB = (int*)p;
    cudaGetSymbolAddress(&p, g_bsum);  int*    bsumB = (int*)p;
    cudaGetSymbolAddress(&p, g_waug0); __half* waug0B = (__half*)p;
    cudaGetSymbolAddress(&p, g_waug1); __half* waug1B = (__half*)p;

    cudaFuncSetAttribute(gemm_mma<true>,  cudaFuncAttributeMaxDynamicSharedMemorySize, SMEM_MMA);
    cudaFuncSetAttribute(gemm_mma<false>, cudaFuncAttributeMaxDynamicSharedMemorySize, SMEM_MMA);

    const int TB = 256;
    const int gMma   = (n + 127) / 128;
    const int gNodeW = (n + 7) / 8;
    const int gEdge  = (tot + TB - 1) / TB;
    const int gScan  = (n + 255) / 256;

    // #1-3, then gemm_mma at #4 (ncu samples launch #4)
    build_waug2<<<130 + gScan, 256>>>(W0, as0, ad0, W1, as1, ad1,
                                      waug0B, waug1B, degB, n);
    decode_edges<<<gEdge, TB>>>(ei, srcB, dstB, degB, e, n);
    scan1<<<gScan, 256>>>(degB, inclB, bsumB, n);
    gemm_mma<true><<<gMma, TB, SMEM_MMA>>>(x, waug0B, hhB, alsB, aldB, n);

    // ---- finish CSR build ----
    scan2<<<1, 512>>>(bsumB, gScan);
    scan3<<<gScan, 256>>>(inclB, degB, bsumB, offB, woffB, n, tot);
    scatter_csr<<<gEdge, TB>>>(srcB, dstB, woffB, csrB, tot);

    // ---- layer 0 aggregation ----
    csr_layer<<<gNodeW, TB>>>(offB, csrB, alsB, aldB, hhB, b0, gg0, be0, m0, v0, xhB,
                              nullptr, nullptr, nullptr, nullptr, nullptr, nullptr, n);

    // ---- layer 1 (fused layer-2 projection in epilogue) ----
    gemm_mma<false><<<gMma, TB, SMEM_MMA>>>(xhB, waug1B, hhB, alsB, aldB, n);
    csr_layer<<<gNodeW, TB>>>(offB, csrB, alsB, aldB, hhB, b1, gg1, be1, m1, v1, xhB,
                              W2, as2, ad2, h2B, als2B, ald2B, n);

    // ---- layer 2 aggregation ----
    csr_out<<<gNodeW, TB>>>(offB, csrB, als2B, ald2B, h2B, b2, out, n);
}

// round 13
// speedup vs baseline: 1.3137x; 1.3137x over previous
#include <cuda_runtime.h>
#include <cuda_fp16.h>
#include <math.h>

#define NN 100000
#define EE 1600000
#define ENE (EE + NN)
#define NAUG 136          // 128 H cols + 4 als + 4 ald
#define BSTRIDE 136       // smem row stride (halfs): 272B, conflict-free
#define SMEM_MMA (2 * 128 * 136 * 2)   // A + B tiles in halfs -> bytes

// ---------------- scratch (device globals; no allocation allowed) ----------
__device__ __half g_hh[NN * 128];   // projected features (fp16)
__device__ __half g_xh[NN * 128];   // activations (fp16)
__device__ float  g_h2[NN * 2];     // layer-2 projected features
__device__ float  g_als[NN * 4];    // per-node src attention logits
__device__ float  g_ald[NN * 4];    // per-node dst attention logits
__device__ float  g_als2[NN];       // layer-2 src logits
__device__ float  g_ald2[NN];       // layer-2 dst logits
__device__ int    g_src[ENE];       // decoded src indices (+self loops)
__device__ int    g_dst[ENE];       // decoded dst indices (+self loops)
__device__ int    g_csr[ENE];       // src indices sorted by dst
__device__ int    g_off[NN + 1];    // CSR row offsets (by dst)
__device__ int    g_deg[NN];        // degree count
__device__ int    g_incl[NN];       // block-inclusive scan scratch
__device__ int    g_woff[NN];       // scatter write cursors
__device__ int    g_bsum[512];      // block sums
__device__ __half g_waug0[128 * NAUG]; // augmented fp16 weights layer 0
__device__ __half g_waug1[128 * NAUG]; // augmented fp16 weights layer 1

// ---------------- helpers ---------------------------------------------------
__device__ __forceinline__ float lrelu(float v) { return v > 0.0f ? v : 0.2f * v; }

__device__ __forceinline__ void ldsm_x4(unsigned* r, unsigned addr) {
    asm volatile("ldmatrix.sync.aligned.m8n8.x4.shared.b16 {%0,%1,%2,%3}, [%4];"
        : "=r"(r[0]), "=r"(r[1]), "=r"(r[2]), "=r"(r[3]) : "r"(addr));
}
__device__ __forceinline__ void ldsm_x4_trans(unsigned* r, unsigned addr) {
    asm volatile("ldmatrix.sync.aligned.m8n8.x4.trans.shared.b16 {%0,%1,%2,%3}, [%4];"
        : "=r"(r[0]), "=r"(r[1]), "=r"(r[2]), "=r"(r[3]) : "r"(addr));
}
__device__ __forceinline__ void ldsm_x2_trans(unsigned* r, unsigned addr) {
    asm volatile("ldmatrix.sync.aligned.m8n8.x2.trans.shared.b16 {%0,%1}, [%2];"
        : "=r"(r[0]), "=r"(r[1]) : "r"(addr));
}
__device__ __forceinline__ void mma16816(float* d, const unsigned* a, const unsigned* b) {
    asm volatile("mma.sync.aligned.m16n8k16.row.col.f32.f16.f16.f32 "
        "{%0,%1,%2,%3}, {%4,%5,%6,%7}, {%8,%9}, {%0,%1,%2,%3};"
        : "+f"(d[0]), "+f"(d[1]), "+f"(d[2]), "+f"(d[3])
        : "r"(a[0]), "r"(a[1]), "r"(a[2]), "r"(a[3]), "r"(b[0]), "r"(b[1]));
}
__device__ __forceinline__ float4 h4f(uint2 u) {
    __half2 p0 = *(__half2*)&u.x, p1 = *(__half2*)&u.y;
    float2 f0 = __half22float2(p0), f1 = __half22float2(p1);
    return make_float4(f0.x, f0.y, f1.x, f1.y);
}
__device__ __forceinline__ void cpasync16(unsigned daddr, const void* g, unsigned srcsz) {
    asm volatile("cp.async.ca.shared.global [%0], [%1], 16, %2;"
                 :: "r"(daddr), "l"(g), "r"(srcsz));
}

// ---------------- augmented weights (both layers) + deg zero -----------------
__global__ void build_waug2(const float* __restrict__ W0, const float* __restrict__ as0,
                            const float* __restrict__ ad0, const float* __restrict__ W1,
                            const float* __restrict__ as1, const float* __restrict__ ad1,
                            __half* __restrict__ wg0, __half* __restrict__ wg1,
                            int* deg, int n) {
    int b = blockIdx.x, t = threadIdx.x;
    if (b < 130) {
        const float* W  = (b < 65) ? W0 : W1;
        const float* as = (b < 65) ? as0 : as1;
        const float* ad = (b < 65) ? ad0 : ad1;
        __half* wg = (b < 65) ? wg0 : wg1;
        int bb = (b < 65) ? b : b - 65;
        if (bb < 64) {
            int i = bb * 256 + t;
            wg[(i >> 7) * NAUG + (i & 127)] = __float2half(W[i]);
        } else {
#pragma unroll
            for (int j = 0; j < 4; j++) {
                int idx = j * 256 + t;
                int k = idx >> 3, hcol = idx & 7;
                int h = hcol & 3;
                const float* av = (hcol < 4) ? as : ad;
                float sum = 0.f;
#pragma unroll
                for (int cc = 0; cc < 32; cc++)
                    sum += W[k * 128 + h * 32 + cc] * av[h * 32 + cc];
                wg[k * NAUG + 128 + ((hcol < 4) ? 0 : 4) + h] = __float2half(sum);
            }
        }
    } else {
        int i = (b - 130) * 256 + t;
        if (i < n) deg[i] = 0;
    }
}

// ---------------- decode + inline dtype detection + degree count -------------
__device__ __forceinline__ int detect_is64(const unsigned* w, int e) {
    int allz = 1;
#pragma unroll
    for (int k = 0; k < 8; k++) {
        long long idx = 2LL * (((long long)k * e) / 8) + 1;
        allz &= (w[idx] == 0u) ? 1 : 0;
    }
    return allz;
}

__global__ void decode_edges(const void* __restrict__ ei, int* __restrict__ src,
                             int* __restrict__ dst, int* deg, int e, int n) {
    int i = blockIdx.x * blockDim.x + threadIdx.x;
    if (i >= e + n) return;
    int s, d;
    if (i < e) {
        if (detect_is64((const unsigned*)ei, e)) {
            const long long* p = (const long long*)ei;
            s = (int)p[i]; d = (int)p[e + i];
        } else {
            const int* p = (const int*)ei;
            s = p[i]; d = p[e + i];
        }
    } else {
        s = d = i - e;
    }
    src[i] = s;
    dst[i] = d;
    atomicAdd(&deg[d], 1);
}

// block-inclusive scan (256/block) + block sums
__global__ void scan1(const int* __restrict__ deg, int* __restrict__ incl,
                      int* __restrict__ bsum, int n) {
    __shared__ int sm[256];
    int i = blockIdx.x * 256 + threadIdx.x;
    int v = (i < n) ? deg[i] : 0;
    sm[threadIdx.x] = v;
    __syncthreads();
#pragma unroll
    for (int o = 1; o < 256; o <<= 1) {
        int t = (threadIdx.x >= o) ? sm[threadIdx.x - o] : 0;
        __syncthreads();
        sm[threadIdx.x] += t;
        __syncthreads();
    }
    if (i < n) incl[i] = sm[threadIdx.x];
    if (threadIdx.x == 255) bsum[blockIdx.x] = sm[255];
}

// offsets + write cursors; block-sum prefix computed locally (nb <= 512)
__global__ void scan3(const int* __restrict__ incl, const int* __restrict__ deg,
                      const int* __restrict__ bsum, int* __restrict__ off,
                      int* __restrict__ woff, int n, int tot, int nb) {
    __shared__ int pre;   // sum of bsum[0..blockIdx.x-1]
    int i = blockIdx.x * blockDim.x + threadIdx.x;
    // cooperative partial sum of bsum prefix across first 256 threads
    __shared__ int part[256];
    int tsum = 0;
    for (int k = threadIdx.x; k < blockIdx.x; k += 256) tsum += bsum[k];
    part[threadIdx.x] = tsum;
    __syncthreads();
    if (threadIdx.x < 128) part[threadIdx.x] += part[threadIdx.x + 128];
    __syncthreads();
    if (threadIdx.x < 64) part[threadIdx.x] += part[threadIdx.x + 64];
    __syncthreads();
    if (threadIdx.x < 32) {
        int v = part[threadIdx.x] + part[threadIdx.x + 32];
#pragma unroll
        for (int o = 16; o > 0; o >>= 1) v += __shfl_down_sync(0xffffffffu, v, o);
        if (threadIdx.x == 0) pre = v;
    }
    __syncthreads();
    if (i >= n) return;
    int o = incl[i] - deg[i] + pre;
    off[i] = o;
    woff[i] = o;
    if (i == 0) off[n] = tot;
}

__global__ void scatter_csr(const int* __restrict__ src, const int* __restrict__ dst,
                            int* woff, int* __restrict__ csr, int tot) {
    int i = blockIdx.x * blockDim.x + threadIdx.x;
    if (i >= tot) return;
    int pos = atomicAdd(&woff[dst[i]], 1);
    csr[pos] = src[i];
}

// ---------------- tensor-core GEMM: [H | als | ald] = X @ W' -----------------
template <bool FP32IN>
__global__ void __launch_bounds__(256, 2) gemm_mma(const void* __restrict__ Xv,
                                                   const __half* __restrict__ waug,
                                                   __half* __restrict__ Hout,
                                                   float* __restrict__ als,
                                                   float* __restrict__ ald, int n) {
    extern __shared__ __half smh[];
    __half* As = smh;
    __half* Bs = smh + 128 * BSTRIDE;
    const int t = threadIdx.x;
    const int w = t >> 5, lane = t & 31;
    const int row0 = blockIdx.x * 128;

    const unsigned As_base = (unsigned)__cvta_generic_to_shared(As);
    const unsigned Bs_base = (unsigned)__cvta_generic_to_shared(Bs);

    for (int i = t; i < 2176; i += 256)
        cpasync16(Bs_base + i * 16, (const uint4*)waug + i, 16u);

    if (FP32IN) {
        const float* X = (const float*)Xv;
        for (int i = t; i < 128 * 16; i += 256) {
            int r = i >> 4, q = i & 15;
            float4 v0 = make_float4(0.f, 0.f, 0.f, 0.f), v1 = v0;
            if (row0 + r < n) {
                v0 = ((const float4*)X)[(size_t)(row0 + r) * 32 + q * 2];
                v1 = ((const float4*)X)[(size_t)(row0 + r) * 32 + q * 2 + 1];
            }
            __half2 h0 = __floats2half2_rn(v0.x, v0.y), h1 = __floats2half2_rn(v0.z, v0.w);
            __half2 h2 = __floats2half2_rn(v1.x, v1.y), h3 = __floats2half2_rn(v1.z, v1.w);
            uint4 pk = make_uint4(*(unsigned*)&h0, *(unsigned*)&h1,
                                  *(unsigned*)&h2, *(unsigned*)&h3);
            *(uint4*)(As + r * BSTRIDE + q * 8) = pk;
        }
    } else {
        const __half* Xh = (const __half*)Xv;
        for (int i = t; i < 128 * 16; i += 256) {
            int r = i >> 4, q = i & 15;
            unsigned sz = (row0 + r < n) ? 16u : 0u;
            cpasync16(As_base + (r * BSTRIDE + q * 8) * 2,
                      (const uint4*)Xh + (size_t)(row0 + r) * 16 + q, sz);
        }
    }
    asm volatile("cp.async.commit_group;");
    asm volatile("cp.async.wait_group 0;" ::: "memory");
    __syncthreads();

    float d[17][4] = {};
#pragma unroll
    for (int kt = 0; kt < 8; kt++) {
        unsigned a[4];
        ldsm_x4(a, As_base +
            (unsigned)(((w * 16 + (lane & 15)) * BSTRIDE + kt * 16 + (lane >> 4) * 8) * 2));
        unsigned b[17][2];
#pragma unroll
        for (int np = 0; np < 8; np++) {
            unsigned r[4];
            ldsm_x4_trans(r, Bs_base +
                (unsigned)(((kt * 16 + (lane & 15)) * BSTRIDE + np * 16 + (lane >> 4) * 8) * 2));
            b[2 * np][0] = r[0]; b[2 * np][1] = r[1];
            b[2 * np + 1][0] = r[2]; b[2 * np + 1][1] = r[3];
        }
        ldsm_x2_trans(b[16], Bs_base +
            (unsigned)(((kt * 16 + (lane & 15)) * BSTRIDE + 128) * 2));
#pragma unroll
        for (int nt = 0; nt < 17; nt++) mma16816(d[nt], a, b[nt]);
    }

    const int g = lane >> 2, i2 = lane & 3;
    const int r0 = row0 + w * 16 + g, r1 = r0 + 8;
#pragma unroll
    for (int nt = 0; nt < 16; nt++) {
        int c = nt * 8 + 2 * i2;
        if (r0 < n) *(__half2*)&Hout[(size_t)r0 * 128 + c] = __floats2half2_rn(d[nt][0], d[nt][1]);
        if (r1 < n) *(__half2*)&Hout[(size_t)r1 * 128 + c] = __floats2half2_rn(d[nt][2], d[nt][3]);
    }
    {
        int j = 2 * i2;
        float* pp = (j < 4) ? als : ald;
        int jj = j & 3;
        if (r0 < n) { pp[r0 * 4 + jj] = d[16][0]; pp[r0 * 4 + jj + 1] = d[16][1]; }
        if (r1 < n) { pp[r1 * 4 + jj] = d[16][2]; pp[r1 * 4 + jj + 1] = d[16][3]; }
    }
}

// ---------------- CSR aggregation + softmax + bias + BN + ELU (fused) --------
// direct register gather, warp per dst node, edge loop unrolled 4x (R11 form)
__global__ void csr_layer(const int* __restrict__ off, const int* __restrict__ csr,
                          const float* __restrict__ als, const float* __restrict__ ald,
                          const __half* __restrict__ Hm,
                          const float* __restrict__ b, const float* __restrict__ gm,
                          const float* __restrict__ be, const float* __restrict__ mu,
                          const float* __restrict__ var,
                          __half* __restrict__ xo,
                          const float* __restrict__ W2, const float* __restrict__ as2,
                          const float* __restrict__ ad2, float* __restrict__ h2,
                          float* __restrict__ als2, float* __restrict__ ald2, int n) {
    int d = (blockIdx.x * blockDim.x + threadIdx.x) >> 5;
    int lane = threadIdx.x & 31;
    if (d >= n) return;
    const int head = lane >> 3;
    const int beg = off[d], end = off[d + 1];
    const float aldv = ald[d * 4 + head];
    const uint2* H2v = (const uint2*)Hm;

    float4 a = make_float4(0.f, 0.f, 0.f, 0.f);
    float den = 0.f;
    int j = beg;
    for (; j + 4 <= end; j += 4) {
        int s0 = csr[j], s1 = csr[j + 1], s2 = csr[j + 2], s3 = csr[j + 3];
        float l0 = als[s0 * 4 + head];
        float l1 = als[s1 * 4 + head];
        float l2 = als[s2 * 4 + head];
        float l3 = als[s3 * 4 + head];
        uint2 u0 = H2v[(size_t)s0 * 32 + lane];
        uint2 u1 = H2v[(size_t)s1 * 32 + lane];
        uint2 u2 = H2v[(size_t)s2 * 32 + lane];
        uint2 u3 = H2v[(size_t)s3 * 32 + lane];
        float e0 = __expf(lrelu(l0 + aldv));
        float e1 = __expf(lrelu(l1 + aldv));
        float e2 = __expf(lrelu(l2 + aldv));
        float e3 = __expf(lrelu(l3 + aldv));
        float4 h0 = h4f(u0), h1 = h4f(u1), h2f_ = h4f(u2), h3 = h4f(u3);
        a.x += h0.x * e0 + h1.x * e1 + h2f_.x * e2 + h3.x * e3;
        a.y += h0.y * e0 + h1.y * e1 + h2f_.y * e2 + h3.y * e3;
        a.z += h0.z * e0 + h1.z * e1 + h2f_.z * e2 + h3.z * e3;
        a.w += h0.w * e0 + h1.w * e1 + h2f_.w * e2 + h3.w * e3;
        den += e0 + e1 + e2 + e3;
    }
    for (; j < end; j++) {
        int s = csr[j];
        float ee = __expf(lrelu(als[s * 4 + head] + aldv));
        float4 hv = h4f(H2v[(size_t)s * 32 + lane]);
        a.x += hv.x * ee;
        a.y += hv.y * ee;
        a.z += hv.z * ee;
        a.w += hv.w * ee;
        den += ee;
    }
    float inv = 1.0f / (den + 1e-16f);
    float4 b4  = ((const float4*)b)[lane];
    float4 gm4 = ((const float4*)gm)[lane];
    float4 be4 = ((const float4*)be)[lane];
    float4 mu4 = ((const float4*)mu)[lane];
    float4 v4  = ((const float4*)var)[lane];
    float4 o;
    float t;
    t = a.x * inv + b4.x; t = (t - mu4.x) * rsqrtf(v4.x + 1e-5f) * gm4.x + be4.x; o.x = t > 0.f ? t : expm1f(t);
    t = a.y * inv + b4.y; t = (t - mu4.y) * rsqrtf(v4.y + 1e-5f) * gm4.y + be4.y; o.y = t > 0.f ? t : expm1f(t);
    t = a.z * inv + b4.z; t = (t - mu4.z) * rsqrtf(v4.z + 1e-5f) * gm4.z + be4.z; o.z = t > 0.f ? t : expm1f(t);
    t = a.w * inv + b4.w; t = (t - mu4.w) * rsqrtf(v4.w + 1e-5f) * gm4.w + be4.w; o.w = t > 0.f ? t : expm1f(t);
    __half2 p0 = __floats2half2_rn(o.x, o.y), p1 = __floats2half2_rn(o.z, o.w);
    ((uint2*)xo)[(size_t)d * 32 + lane] = make_uint2(*(unsigned*)&p0, *(unsigned*)&p1);

    if (W2) {  // fused layer-2 projection
        float4 w0 = ((const float4*)W2)[lane * 2];
        float4 w1 = ((const float4*)W2)[lane * 2 + 1];
        float c0 = o.x * w0.x + o.y * w0.z + o.z * w1.x + o.w * w1.z;
        float c1 = o.x * w0.y + o.y * w0.w + o.z * w1.y + o.w * w1.w;
#pragma unroll
        for (int oo = 16; oo > 0; oo >>= 1) {
            c0 += __shfl_down_sync(0xffffffffu, c0, oo);
            c1 += __shfl_down_sync(0xffffffffu, c1, oo);
        }
        if (lane == 0) {
            h2[d * 2]     = c0;
            h2[d * 2 + 1] = c1;
            als2[d] = c0 * as2[0] + c1 * as2[1];
            ald2[d] = c0 * ad2[0] + c1 * ad2[1];
        }
    }
}

// ---------------- CSR output aggregation (warp per dst, lanes over edges) ----
__global__ void csr_out(const int* __restrict__ off, const int* __restrict__ csr,
                        const float* __restrict__ als, const float* __restrict__ ald,
                        const float* __restrict__ h2, const float* __restrict__ b2,
                        float* __restrict__ out, int n) {
    int d = (blockIdx.x * blockDim.x + threadIdx.x) >> 5;
    int lane = threadIdx.x & 31;
    if (d >= n) return;
    const int beg = off[d], end = off[d + 1];
    const float aldv = ald[d];
    float a0 = 0.f, a1 = 0.f, den = 0.f;
    for (int j = beg + lane; j < end; j += 32) {
        int s = csr[j];
        float ee = __expf(lrelu(als[s] + aldv));
        float2 hv = ((const float2*)h2)[s];
        a0 += hv.x * ee;
        a1 += hv.y * ee;
        den += ee;
    }
#pragma unroll
    for (int o = 16; o > 0; o >>= 1) {
        a0  += __shfl_down_sync(0xffffffffu, a0, o);
        a1  += __shfl_down_sync(0xffffffffu, a1, o);
        den += __shfl_down_sync(0xffffffffu, den, o);
    }
    if (lane == 0) {
        float inv = 1.0f / (den + 1e-16f);
        out[d * 2]     = a0 * inv + b2[0];
        out[d * 2 + 1] = a1 * inv + b2[1];
    }
}

// ---------------- host ------------------------------------------------------
extern "C" void kernel_launch(void* const* d_in, const int* in_sizes, int n_in,
                              void* d_out, int out_size) {
    const float* x  = (const float*)d_in[0];
    const void*  ei = d_in[1];
    const float *W0 = (const float*)d_in[2],  *as0 = (const float*)d_in[3],
                *ad0 = (const float*)d_in[4], *b0 = (const float*)d_in[5],
                *gg0 = (const float*)d_in[6], *be0 = (const float*)d_in[7],
                *m0 = (const float*)d_in[8],  *v0 = (const float*)d_in[9];
    const float *W1 = (const float*)d_in[10], *as1 = (const float*)d_in[11],
                *ad1 = (const float*)d_in[12],*b1 = (const float*)d_in[13],
                *gg1 = (const float*)d_in[14],*be1 = (const float*)d_in[15],
                *m1 = (const float*)d_in[16], *v1 = (const float*)d_in[17];
    const float *W2 = (const float*)d_in[18], *as2 = (const float*)d_in[19],
                *ad2 = (const float*)d_in[20],*b2 = (const float*)d_in[21];
    float* out = (float*)d_out;

    const int n = in_sizes[0] / 128;
    const int e = in_sizes[1] / 2;
    const int tot = e + n;

    void* p;
    cudaGetSymbolAddress(&p, g_hh);    __half* hhB   = (__half*)p;
    cudaGetSymbolAddress(&p, g_xh);    __half* xhB   = (__half*)p;
    cudaGetSymbolAddress(&p, g_h2);    float*  h2B   = (float*)p;
    cudaGetSymbolAddress(&p, g_als);   float*  alsB  = (float*)p;
    cudaGetSymbolAddress(&p, g_ald);   float*  aldB  = (float*)p;
    cudaGetSymbolAddress(&p, g_als2);  float*  als2B = (float*)p;
    cudaGetSymbolAddress(&p, g_ald2);  float*  ald2B = (float*)p;
    cudaGetSymbolAddress(&p, g_src);   int*    srcB  = (int*)p;
    cudaGetSymbolAddress(&p, g_dst);   int*    dstB  = (int*)p;
    cudaGetSymbolAddress(&p, g_csr);   int*    csrB  = (int*)p;
    cudaGetSymbolAddress(&p, g_off);   int*    offB  = (int*)p;
    cudaGetSymbolAddress(&p, g_deg);   int*    degB  = (int*)p;
    cudaGetSymbolAddress(&p, g_incl);  int*    inclB = (int*)p;
    cudaGetSymbolAddress(&p, g_woff);  int*    woffB = (int*)p;
    cudaGetSymbolAddress(&p, g_bsum);  int*    bsumB = (int*)p;
    cudaGetSymbolAddress(&p, g_waug0); __half* waug0B = (__half*)p;
    cudaGetSymbolAddress(&p, g_waug1); __half* waug1B = (__half*)p;

    cudaFuncSetAttribute(gemm_mma<true>,  cudaFuncAttributeMaxDynamicSharedMemorySize, SMEM_MMA);
    cudaFuncSetAttribute(gemm_mma<false>, cudaFuncAttributeMaxDynamicSharedMemorySize, SMEM_MMA);

    const int TB = 256;
    const int gMma   = (n + 127) / 128;
    const int gNodeW = (n + 7) / 8;
    const int gEdge  = (tot + TB - 1) / TB;
    const int gScan  = (n + 255) / 256;

    // #1-3, then gemm_mma at #4 (ncu samples launch #4)
    build_waug2<<<130 + gScan, 256>>>(W0, as0, ad0, W1, as1, ad1,
                                      waug0B, waug1B, degB, n);
    decode_edges<<<gEdge, TB>>>(ei, srcB, dstB, degB, e, n);
    scan1<<<gScan, 256>>>(degB, inclB, bsumB, n);
    gemm_mma<true><<<gMma, TB, SMEM_MMA>>>(x, waug0B, hhB, alsB, aldB, n);

    // ---- finish CSR build (scan2 merged into scan3) ----
    scan3<<<gScan, 256>>>(inclB, degB, bsumB, offB, woffB, n, tot, gScan);
    scatter_csr<<<gEdge, TB>>>(srcB, dstB, woffB, csrB, tot);

    // ---- layer 0 aggregation ----
    csr_layer<<<gNodeW, TB>>>(offB, csrB, alsB, aldB, hhB, b0, gg0, be0, m0, v0, xhB,
                              nullptr, nullptr, nullptr, nullptr, nullptr, nullptr, n);

    // ---- layer 1 (fused layer-2 projection in epilogue) ----
    gemm_mma<false><<<gMma, TB, SMEM_MMA>>>(xhB, waug1B, hhB, alsB, aldB, n);
    csr_layer<<<gNodeW, TB>>>(offB, csrB, alsB, aldB, hhB, b1, gg1, be1, m1, v1, xhB,
                              W2, as2, ad2, h2B, als2B, ald2B, n);

    // ---- layer 2 aggregation ----
    csr_out<<<gNodeW, TB>>>(offB, csrB, als2B, ald2B, h2B, b2, out, n);
}

// round 14
// speedup vs baseline: 1.3306x; 1.0128x over previous
#include <cuda_runtime.h>
#include <cuda_fp16.h>
#include <math.h>

#define NN 100000
#define EE 1600000
#define ENE (EE + NN)
#define NAUG 136          // 128 H cols + 4 als + 4 ald
#define BSTRIDE 136       // smem row stride (halfs): 272B, conflict-free
#define SMEM_MMA (2 * 128 * 136 * 2)   // A + B tiles in halfs -> bytes

// ---------------- scratch (device globals; no allocation allowed) ----------
__device__ __half g_hh[NN * 128];   // projected features (fp16)
__device__ __half g_xh[NN * 128];   // activations (fp16)
__device__ float  g_h2[NN * 2];     // layer-2 projected features
__device__ float  g_als[NN * 4];    // per-node src attention logits
__device__ float  g_ald[NN * 4];    // per-node dst attention logits
__device__ float  g_als2[NN];       // layer-2 src logits
__device__ float  g_ald2[NN];       // layer-2 dst logits
__device__ int    g_src[ENE];       // decoded src indices (+self loops)
__device__ int    g_dst[ENE];       // decoded dst indices (+self loops)
__device__ int    g_csr[ENE];       // src indices sorted by dst
__device__ int    g_off[NN + 1];    // CSR row offsets (by dst)
__device__ int    g_deg[NN];        // degree count
__device__ int    g_incl[NN];       // block-inclusive scan scratch
__device__ int    g_woff[NN];       // scatter write cursors
__device__ int    g_bsum[512];      // block sums
__device__ __half g_waug0[128 * NAUG]; // augmented fp16 weights layer 0
__device__ __half g_waug1[128 * NAUG]; // augmented fp16 weights layer 1

// ---------------- streams for fork-join overlap (created pre-main) ----------
struct StreamInit {
    cudaStream_t s2 = nullptr;
    cudaEvent_t evA = nullptr, evB = nullptr;
    bool ok = false;
    StreamInit() {
        ok = (cudaStreamCreateWithFlags(&s2, cudaStreamNonBlocking) == cudaSuccess) &&
             (cudaEventCreateWithFlags(&evA, cudaEventDisableTiming) == cudaSuccess) &&
             (cudaEventCreateWithFlags(&evB, cudaEventDisableTiming) == cudaSuccess);
    }
};
static StreamInit g_si;

// ---------------- helpers ---------------------------------------------------
__device__ __forceinline__ float lrelu(float v) { return v > 0.0f ? v : 0.2f * v; }

__device__ __forceinline__ void ldsm_x4(unsigned* r, unsigned addr) {
    asm volatile("ldmatrix.sync.aligned.m8n8.x4.shared.b16 {%0,%1,%2,%3}, [%4];"
        : "=r"(r[0]), "=r"(r[1]), "=r"(r[2]), "=r"(r[3]) : "r"(addr));
}
__device__ __forceinline__ void ldsm_x4_trans(unsigned* r, unsigned addr) {
    asm volatile("ldmatrix.sync.aligned.m8n8.x4.trans.shared.b16 {%0,%1,%2,%3}, [%4];"
        : "=r"(r[0]), "=r"(r[1]), "=r"(r[2]), "=r"(r[3]) : "r"(addr));
}
__device__ __forceinline__ void ldsm_x2_trans(unsigned* r, unsigned addr) {
    asm volatile("ldmatrix.sync.aligned.m8n8.x2.trans.shared.b16 {%0,%1}, [%2];"
        : "=r"(r[0]), "=r"(r[1]) : "r"(addr));
}
__device__ __forceinline__ void mma16816(float* d, const unsigned* a, const unsigned* b) {
    asm volatile("mma.sync.aligned.m16n8k16.row.col.f32.f16.f16.f32 "
        "{%0,%1,%2,%3}, {%4,%5,%6,%7}, {%8,%9}, {%0,%1,%2,%3};"
        : "+f"(d[0]), "+f"(d[1]), "+f"(d[2]), "+f"(d[3])
        : "r"(a[0]), "r"(a[1]), "r"(a[2]), "r"(a[3]), "r"(b[0]), "r"(b[1]));
}
__device__ __forceinline__ float4 h4f(uint2 u) {
    __half2 p0 = *(__half2*)&u.x, p1 = *(__half2*)&u.y;
    float2 f0 = __half22float2(p0), f1 = __half22float2(p1);
    return make_float4(f0.x, f0.y, f1.x, f1.y);
}
__device__ __forceinline__ void cpasync16(unsigned daddr, const void* g, unsigned srcsz) {
    asm volatile("cp.async.ca.shared.global [%0], [%1], 16, %2;"
                 :: "r"(daddr), "l"(g), "r"(srcsz));
}

// ---------------- augmented weights (both layers) + deg zero -----------------
__global__ void build_waug2(const float* __restrict__ W0, const float* __restrict__ as0,
                            const float* __restrict__ ad0, const float* __restrict__ W1,
                            const float* __restrict__ as1, const float* __restrict__ ad1,
                            __half* __restrict__ wg0, __half* __restrict__ wg1,
                            int* deg, int n) {
    int b = blockIdx.x, t = threadIdx.x;
    if (b < 130) {
        const float* W  = (b < 65) ? W0 : W1;
        const float* as = (b < 65) ? as0 : as1;
        const float* ad = (b < 65) ? ad0 : ad1;
        __half* wg = (b < 65) ? wg0 : wg1;
        int bb = (b < 65) ? b : b - 65;
        if (bb < 64) {
            int i = bb * 256 + t;
            wg[(i >> 7) * NAUG + (i & 127)] = __float2half(W[i]);
        } else {
#pragma unroll
            for (int j = 0; j < 4; j++) {
                int idx = j * 256 + t;
                int k = idx >> 3, hcol = idx & 7;
                int h = hcol & 3;
                const float* av = (hcol < 4) ? as : ad;
                float sum = 0.f;
#pragma unroll
                for (int cc = 0; cc < 32; cc++)
                    sum += W[k * 128 + h * 32 + cc] * av[h * 32 + cc];
                wg[k * NAUG + 128 + ((hcol < 4) ? 0 : 4) + h] = __float2half(sum);
            }
        }
    } else {
        int i = (b - 130) * 256 + t;
        if (i < n) deg[i] = 0;
    }
}

// ---------------- decode + inline dtype detection + degree count -------------
__device__ __forceinline__ int detect_is64(const unsigned* w, int e) {
    int allz = 1;
#pragma unroll
    for (int k = 0; k < 8; k++) {
        long long idx = 2LL * (((long long)k * e) / 8) + 1;
        allz &= (w[idx] == 0u) ? 1 : 0;
    }
    return allz;
}

__global__ void decode_edges(const void* __restrict__ ei, int* __restrict__ src,
                             int* __restrict__ dst, int* deg, int e, int n) {
    int i = blockIdx.x * blockDim.x + threadIdx.x;
    if (i >= e + n) return;
    int s, d;
    if (i < e) {
        if (detect_is64((const unsigned*)ei, e)) {
            const long long* p = (const long long*)ei;
            s = (int)p[i]; d = (int)p[e + i];
        } else {
            const int* p = (const int*)ei;
            s = p[i]; d = p[e + i];
        }
    } else {
        s = d = i - e;
    }
    src[i] = s;
    dst[i] = d;
    atomicAdd(&deg[d], 1);
}

// block-inclusive scan (256/block) + block sums
__global__ void scan1(const int* __restrict__ deg, int* __restrict__ incl,
                      int* __restrict__ bsum, int n) {
    __shared__ int sm[256];
    int i = blockIdx.x * 256 + threadIdx.x;
    int v = (i < n) ? deg[i] : 0;
    sm[threadIdx.x] = v;
    __syncthreads();
#pragma unroll
    for (int o = 1; o < 256; o <<= 1) {
        int t = (threadIdx.x >= o) ? sm[threadIdx.x - o] : 0;
        __syncthreads();
        sm[threadIdx.x] += t;
        __syncthreads();
    }
    if (i < n) incl[i] = sm[threadIdx.x];
    if (threadIdx.x == 255) bsum[blockIdx.x] = sm[255];
}

// offsets + write cursors; block-sum prefix computed locally (nb <= 512)
__global__ void scan3(const int* __restrict__ incl, const int* __restrict__ deg,
                      const int* __restrict__ bsum, int* __restrict__ off,
                      int* __restrict__ woff, int n, int tot, int nb) {
    __shared__ int pre;
    __shared__ int part[256];
    int i = blockIdx.x * blockDim.x + threadIdx.x;
    int tsum = 0;
    for (int k = threadIdx.x; k < blockIdx.x; k += 256) tsum += bsum[k];
    part[threadIdx.x] = tsum;
    __syncthreads();
    if (threadIdx.x < 128) part[threadIdx.x] += part[threadIdx.x + 128];
    __syncthreads();
    if (threadIdx.x < 64) part[threadIdx.x] += part[threadIdx.x + 64];
    __syncthreads();
    if (threadIdx.x < 32) {
        int v = part[threadIdx.x] + part[threadIdx.x + 32];
#pragma unroll
        for (int o = 16; o > 0; o >>= 1) v += __shfl_down_sync(0xffffffffu, v, o);
        if (threadIdx.x == 0) pre = v;
    }
    __syncthreads();
    if (i >= n) return;
    int o = incl[i] - deg[i] + pre;
    off[i] = o;
    woff[i] = o;
    if (i == 0) off[n] = tot;
}

__global__ void scatter_csr(const int* __restrict__ src, const int* __restrict__ dst,
                            int* woff, int* __restrict__ csr, int tot) {
    int i = blockIdx.x * blockDim.x + threadIdx.x;
    if (i >= tot) return;
    int pos = atomicAdd(&woff[dst[i]], 1);
    csr[pos] = src[i];
}

// ---------------- tensor-core GEMM: [H | als | ald] = X @ W' -----------------
template <bool FP32IN>
__global__ void __launch_bounds__(256, 2) gemm_mma(const void* __restrict__ Xv,
                                                   const __half* __restrict__ waug,
                                                   __half* __restrict__ Hout,
                                                   float* __restrict__ als,
                                                   float* __restrict__ ald, int n) {
    extern __shared__ __half smh[];
    __half* As = smh;
    __half* Bs = smh + 128 * BSTRIDE;
    const int t = threadIdx.x;
    const int w = t >> 5, lane = t & 31;
    const int row0 = blockIdx.x * 128;

    const unsigned As_base = (unsigned)__cvta_generic_to_shared(As);
    const unsigned Bs_base = (unsigned)__cvta_generic_to_shared(Bs);

    for (int i = t; i < 2176; i += 256)
        cpasync16(Bs_base + i * 16, (const uint4*)waug + i, 16u);

    if (FP32IN) {
        const float* X = (const float*)Xv;
        for (int i = t; i < 128 * 16; i += 256) {
            int r = i >> 4, q = i & 15;
            float4 v0 = make_float4(0.f, 0.f, 0.f, 0.f), v1 = v0;
            if (row0 + r < n) {
                v0 = ((const float4*)X)[(size_t)(row0 + r) * 32 + q * 2];
                v1 = ((const float4*)X)[(size_t)(row0 + r) * 32 + q * 2 + 1];
            }
            __half2 h0 = __floats2half2_rn(v0.x, v0.y), h1 = __floats2half2_rn(v0.z, v0.w);
            __half2 h2 = __floats2half2_rn(v1.x, v1.y), h3 = __floats2half2_rn(v1.z, v1.w);
            uint4 pk = make_uint4(*(unsigned*)&h0, *(unsigned*)&h1,
                                  *(unsigned*)&h2, *(unsigned*)&h3);
            *(uint4*)(As + r * BSTRIDE + q * 8) = pk;
        }
    } else {
        const __half* Xh = (const __half*)Xv;
        for (int i = t; i < 128 * 16; i += 256) {
            int r = i >> 4, q = i & 15;
            unsigned sz = (row0 + r < n) ? 16u : 0u;
            cpasync16(As_base + (r * BSTRIDE + q * 8) * 2,
                      (const uint4*)Xh + (size_t)(row0 + r) * 16 + q, sz);
        }
    }
    asm volatile("cp.async.commit_group;");
    asm volatile("cp.async.wait_group 0;" ::: "memory");
    __syncthreads();

    float d[17][4] = {};
#pragma unroll
    for (int kt = 0; kt < 8; kt++) {
        unsigned a[4];
        ldsm_x4(a, As_base +
            (unsigned)(((w * 16 + (lane & 15)) * BSTRIDE + kt * 16 + (lane >> 4) * 8) * 2));
        unsigned b[17][2];
#pragma unroll
        for (int np = 0; np < 8; np++) {
            unsigned r[4];
            ldsm_x4_trans(r, Bs_base +
                (unsigned)(((kt * 16 + (lane & 15)) * BSTRIDE + np * 16 + (lane >> 4) * 8) * 2));
            b[2 * np][0] = r[0]; b[2 * np][1] = r[1];
            b[2 * np + 1][0] = r[2]; b[2 * np + 1][1] = r[3];
        }
        ldsm_x2_trans(b[16], Bs_base +
            (unsigned)(((kt * 16 + (lane & 15)) * BSTRIDE + 128) * 2));
#pragma unroll
        for (int nt = 0; nt < 17; nt++) mma16816(d[nt], a, b[nt]);
    }

    const int g = lane >> 2, i2 = lane & 3;
    const int r0 = row0 + w * 16 + g, r1 = r0 + 8;
#pragma unroll
    for (int nt = 0; nt < 16; nt++) {
        int c = nt * 8 + 2 * i2;
        if (r0 < n) *(__half2*)&Hout[(size_t)r0 * 128 + c] = __floats2half2_rn(d[nt][0], d[nt][1]);
        if (r1 < n) *(__half2*)&Hout[(size_t)r1 * 128 + c] = __floats2half2_rn(d[nt][2], d[nt][3]);
    }
    {
        int j = 2 * i2;
        float* pp = (j < 4) ? als : ald;
        int jj = j & 3;
        if (r0 < n) { pp[r0 * 4 + jj] = d[16][0]; pp[r0 * 4 + jj + 1] = d[16][1]; }
        if (r1 < n) { pp[r1 * 4 + jj] = d[16][2]; pp[r1 * 4 + jj + 1] = d[16][3]; }
    }
}

// ---------------- CSR aggregation + softmax + bias + BN + ELU (fused) --------
// direct register gather; aligned int4 index loads with one-iteration prefetch
__global__ void csr_layer(const int* __restrict__ off, const int* __restrict__ csr,
                          const float* __restrict__ als, const float* __restrict__ ald,
                          const __half* __restrict__ Hm,
                          const float* __restrict__ b, const float* __restrict__ gm,
                          const float* __restrict__ be, const float* __restrict__ mu,
                          const float* __restrict__ var,
                          __half* __restrict__ xo,
                          const float* __restrict__ W2, const float* __restrict__ as2,
                          const float* __restrict__ ad2, float* __restrict__ h2,
                          float* __restrict__ als2, float* __restrict__ ald2, int n) {
    int d = (blockIdx.x * blockDim.x + threadIdx.x) >> 5;
    int lane = threadIdx.x & 31;
    if (d >= n) return;
    const int head = lane >> 3;
    const int beg = off[d], end = off[d + 1];
    const float aldv = ald[d * 4 + head];
    const uint2* H2v = (const uint2*)Hm;

    float4 a = make_float4(0.f, 0.f, 0.f, 0.f);
    float den = 0.f;

    auto one = [&](int s) {
        float ee = __expf(lrelu(als[s * 4 + head] + aldv));
        float4 hv = h4f(H2v[(size_t)s * 32 + lane]);
        a.x += hv.x * ee;
        a.y += hv.y * ee;
        a.z += hv.z * ee;
        a.w += hv.w * ee;
        den += ee;
    };

    int j = beg;
    int jal = (beg + 3) & ~3;          // first 16B-aligned position
    if (jal > end) jal = end;
    for (; j < jal; j++) one(csr[j]);

    int4 nxt = make_int4(0, 0, 0, 0);
    if (j + 4 <= end) nxt = *(const int4*)(csr + j);
    for (; j + 4 <= end; j += 4) {
        int4 cur = nxt;
        if (j + 8 <= end) nxt = *(const int4*)(csr + j + 4);   // prefetch next indices
        float l0 = als[cur.x * 4 + head];
        float l1 = als[cur.y * 4 + head];
        float l2 = als[cur.z * 4 + head];
        float l3 = als[cur.w * 4 + head];
        uint2 u0 = H2v[(size_t)cur.x * 32 + lane];
        uint2 u1 = H2v[(size_t)cur.y * 32 + lane];
        uint2 u2 = H2v[(size_t)cur.z * 32 + lane];
        uint2 u3 = H2v[(size_t)cur.w * 32 + lane];
        float e0 = __expf(lrelu(l0 + aldv));
        float e1 = __expf(lrelu(l1 + aldv));
        float e2 = __expf(lrelu(l2 + aldv));
        float e3 = __expf(lrelu(l3 + aldv));
        float4 h0 = h4f(u0), h1 = h4f(u1), h2f_ = h4f(u2), h3 = h4f(u3);
        a.x += h0.x * e0 + h1.x * e1 + h2f_.x * e2 + h3.x * e3;
        a.y += h0.y * e0 + h1.y * e1 + h2f_.y * e2 + h3.y * e3;
        a.z += h0.z * e0 + h1.z * e1 + h2f_.z * e2 + h3.z * e3;
        a.w += h0.w * e0 + h1.w * e1 + h2f_.w * e2 + h3.w * e3;
        den += e0 + e1 + e2 + e3;
    }
    for (; j < end; j++) one(csr[j]);

    float inv = 1.0f / (den + 1e-16f);
    float4 b4  = ((const float4*)b)[lane];
    float4 gm4 = ((const float4*)gm)[lane];
    float4 be4 = ((const float4*)be)[lane];
    float4 mu4 = ((const float4*)mu)[lane];
    float4 v4  = ((const float4*)var)[lane];
    float4 o;
    float t;
    t = a.x * inv + b4.x; t = (t - mu4.x) * rsqrtf(v4.x + 1e-5f) * gm4.x + be4.x; o.x = t > 0.f ? t : expm1f(t);
    t = a.y * inv + b4.y; t = (t - mu4.y) * rsqrtf(v4.y + 1e-5f) * gm4.y + be4.y; o.y = t > 0.f ? t : expm1f(t);
    t = a.z * inv + b4.z; t = (t - mu4.z) * rsqrtf(v4.z + 1e-5f) * gm4.z + be4.z; o.z = t > 0.f ? t : expm1f(t);
    t = a.w * inv + b4.w; t = (t - mu4.w) * rsqrtf(v4.w + 1e-5f) * gm4.w + be4.w; o.w = t > 0.f ? t : expm1f(t);
    __half2 p0 = __floats2half2_rn(o.x, o.y), p1 = __floats2half2_rn(o.z, o.w);
    ((uint2*)xo)[(size_t)d * 32 + lane] = make_uint2(*(unsigned*)&p0, *(unsigned*)&p1);

    if (W2) {  // fused layer-2 projection
        float4 w0 = ((const float4*)W2)[lane * 2];
        float4 w1 = ((const float4*)W2)[lane * 2 + 1];
        float c0 = o.x * w0.x + o.y * w0.z + o.z * w1.x + o.w * w1.z;
        float c1 = o.x * w0.y + o.y * w0.w + o.z * w1.y + o.w * w1.w;
#pragma unroll
        for (int oo = 16; oo > 0; oo >>= 1) {
            c0 += __shfl_down_sync(0xffffffffu, c0, oo);
            c1 += __shfl_down_sync(0xffffffffu, c1, oo);
        }
        if (lane == 0) {
            h2[d * 2]     = c0;
            h2[d * 2 + 1] = c1;
            als2[d] = c0 * as2[0] + c1 * as2[1];
            ald2[d] = c0 * ad2[0] + c1 * ad2[1];
        }
    }
}

// ---------------- CSR output aggregation (warp per dst, lanes over edges) ----
__global__ void csr_out(const int* __restrict__ off, const int* __restrict__ csr,
                        const float* __restrict__ als, const float* __restrict__ ald,
                        const float* __restrict__ h2, const float* __restrict__ b2,
                        float* __restrict__ out, int n) {
    int d = (blockIdx.x * blockDim.x + threadIdx.x) >> 5;
    int lane = threadIdx.x & 31;
    if (d >= n) return;
    const int beg = off[d], end = off[d + 1];
    const float aldv = ald[d];
    float a0 = 0.f, a1 = 0.f, den = 0.f;
    for (int j = beg + lane; j < end; j += 32) {
        int s = csr[j];
        float ee = __expf(lrelu(als[s] + aldv));
        float2 hv = ((const float2*)h2)[s];
        a0 += hv.x * ee;
        a1 += hv.y * ee;
        den += ee;
    }
#pragma unroll
    for (int o = 16; o > 0; o >>= 1) {
        a0  += __shfl_down_sync(0xffffffffu, a0, o);
        a1  += __shfl_down_sync(0xffffffffu, a1, o);
        den += __shfl_down_sync(0xffffffffu, den, o);
    }
    if (lane == 0) {
        float inv = 1.0f / (den + 1e-16f);
        out[d * 2]     = a0 * inv + b2[0];
        out[d * 2 + 1] = a1 * inv + b2[1];
    }
}

// ---------------- host ------------------------------------------------------
extern "C" void kernel_launch(void* const* d_in, const int* in_sizes, int n_in,
                              void* d_out, int out_size) {
    const float* x  = (const float*)d_in[0];
    const void*  ei = d_in[1];
    const float *W0 = (const float*)d_in[2],  *as0 = (const float*)d_in[3],
                *ad0 = (const float*)d_in[4], *b0 = (const float*)d_in[5],
                *gg0 = (const float*)d_in[6], *be0 = (const float*)d_in[7],
                *m0 = (const float*)d_in[8],  *v0 = (const float*)d_in[9];
    const float *W1 = (const float*)d_in[10], *as1 = (const float*)d_in[11],
                *ad1 = (const float*)d_in[12],*b1 = (const float*)d_in[13],
                *gg1 = (const float*)d_in[14],*be1 = (const float*)d_in[15],
                *m1 = (const float*)d_in[16], *v1 = (const float*)d_in[17];
    const float *W2 = (const float*)d_in[18], *as2 = (const float*)d_in[19],
                *ad2 = (const float*)d_in[20],*b2 = (const float*)d_in[21];
    float* out = (float*)d_out;

    const int n = in_sizes[0] / 128;
    const int e = in_sizes[1] / 2;
    const int tot = e + n;

    void* p;
    cudaGetSymbolAddress(&p, g_hh);    __half* hhB   = (__half*)p;
    cudaGetSymbolAddress(&p, g_xh);    __half* xhB   = (__half*)p;
    cudaGetSymbolAddress(&p, g_h2);    float*  h2B   = (float*)p;
    cudaGetSymbolAddress(&p, g_als);   float*  alsB  = (float*)p;
    cudaGetSymbolAddress(&p, g_ald);   float*  aldB  = (float*)p;
    cudaGetSymbolAddress(&p, g_als2);  float*  als2B = (float*)p;
    cudaGetSymbolAddress(&p, g_ald2);  float*  ald2B = (float*)p;
    cudaGetSymbolAddress(&p, g_src);   int*    srcB  = (int*)p;
    cudaGetSymbolAddress(&p, g_dst);   int*    dstB  = (int*)p;
    cudaGetSymbolAddress(&p, g_csr);   int*    csrB  = (int*)p;
    cudaGetSymbolAddress(&p, g_off);   int*    offB  = (int*)p;
    cudaGetSymbolAddress(&p, g_deg);   int*    degB  = (int*)p;
    cudaGetSymbolAddress(&p, g_incl);  int*    inclB = (int*)p;
    cudaGetSymbolAddress(&p, g_woff);  int*    woffB = (int*)p;
    cudaGetSymbolAddress(&p, g_bsum);  int*    bsumB = (int*)p;
    cudaGetSymbolAddress(&p, g_waug0); __half* waug0B = (__half*)p;
    cudaGetSymbolAddress(&p, g_waug1); __half* waug1B = (__half*)p;

    cudaFuncSetAttribute(gemm_mma<true>,  cudaFuncAttributeMaxDynamicSharedMemorySize, SMEM_MMA);
    cudaFuncSetAttribute(gemm_mma<false>, cudaFuncAttributeMaxDynamicSharedMemorySize, SMEM_MMA);

    const int TB = 256;
    const int gMma   = (n + 127) / 128;
    const int gNodeW = (n + 7) / 8;
    const int gEdge  = (tot + TB - 1) / TB;
    const int gScan  = (n + 255) / 256;

    const bool fork = g_si.ok;
    cudaStream_t sB = fork ? g_si.s2 : (cudaStream_t)0;

    // prologue: waug + deg zero (both consumers depend on it)
    build_waug2<<<130 + gScan, 256>>>(W0, as0, ad0, W1, as1, ad1,
                                      waug0B, waug1B, degB, n);
    if (fork) {
        cudaEventRecord(g_si.evA, 0);
        cudaStreamWaitEvent(sB, g_si.evA, 0);
    }

    // CSR build chain on sB (parallel with gemm0 on default stream)
    decode_edges<<<gEdge, TB, 0, sB>>>(ei, srcB, dstB, degB, e, n);
    scan1<<<gScan, 256, 0, sB>>>(degB, inclB, bsumB, n);
    scan3<<<gScan, 256, 0, sB>>>(inclB, degB, bsumB, offB, woffB, n, tot, gScan);
    scatter_csr<<<gEdge, TB, 0, sB>>>(srcB, dstB, woffB, csrB, tot);
    if (fork) cudaEventRecord(g_si.evB, sB);

    // layer-0 GEMM on default stream (overlaps CSR build)
    gemm_mma<true><<<gMma, TB, SMEM_MMA>>>(x, waug0B, hhB, alsB, aldB, n);
    if (fork) cudaStreamWaitEvent(0, g_si.evB, 0);

    // ---- layer 0 aggregation ----
    csr_layer<<<gNodeW, TB>>>(offB, csrB, alsB, aldB, hhB, b0, gg0, be0, m0, v0, xhB,
                              nullptr, nullptr, nullptr, nullptr, nullptr, nullptr, n);

    // ---- layer 1 (fused layer-2 projection in epilogue) ----
    gemm_mma<false><<<gMma, TB, SMEM_MMA>>>(xhB, waug1B, hhB, alsB, aldB, n);
    csr_layer<<<gNodeW, TB>>>(offB, csrB, alsB, aldB, hhB, b1, gg1, be1, m1, v1, xhB,
                              W2, as2, ad2, h2B, als2B, ald2B, n);

    // ---- layer 2 aggregation ----
    csr_out<<<gNodeW, TB>>>(offB, csrB, als2B, ald2B, h2B, b2, out, n);
}